// round 2
// baseline (speedup 1.0000x reference)
#include <cuda_runtime.h>
#include <math_constants.h>

#define BDIM 16
#define CDIM 64
#define HW   441
#define NCLS 10
#define MDIM 2205
#define TQ   64
#define TM   128
#define KSPL 32     // k rows of s staged per phase
#define NQT  7      // ceil(441/64)
#define NMT  18     // ceil(2205/128)
#define EPSN 1e-12f

// Scratch (no device allocations allowed)
__device__ float g_qn[BDIM * HW * CDIM];      // normalized queries [b*441+q][c]
__device__ float g_rn[NCLS * MDIM];           // 1/max(||x2[n,:,m]||, eps)
__device__ float g_part[BDIM * NCLS * NQT];   // per-(b,n,qtile) partial sums

// ---------- f32x2 helpers (packed fp32 FMA; only reachable via inline PTX) ----------
__device__ __forceinline__ unsigned long long pk2(float lo, float hi) {
    unsigned long long r;
    unsigned int a = __float_as_uint(lo), b = __float_as_uint(hi);
    asm("mov.b64 %0, {%1, %2};" : "=l"(r) : "r"(a), "r"(b));
    return r;
}
__device__ __forceinline__ void upk2(unsigned long long v, float &lo, float &hi) {
    unsigned int a, b;
    asm("mov.b64 {%0, %1}, %2;" : "=r"(a), "=r"(b) : "l"(v));
    lo = __uint_as_float(a); hi = __uint_as_float(b);
}
__device__ __forceinline__ unsigned long long ffma2(unsigned long long a,
                                                    unsigned long long b,
                                                    unsigned long long c) {
    unsigned long long d;
    asm("fma.rn.f32x2 %0, %1, %2, %3;" : "=l"(d) : "l"(a), "l"(b), "l"(c));
    return d;
}

// Insert v into sorted-descending triple (a0 >= a1 >= a2): 5 FMNMX (alu pipe).
__device__ __forceinline__ void ins3(float v, float &a0, float &a1, float &a2) {
    float n0 = fminf(a0, v); a0 = fmaxf(a0, v);
    float n1 = fminf(a1, n0); a1 = fmaxf(a1, n0);
    a2 = fmaxf(a2, n1);
}

// ---------- preprocessing ----------
__global__ void norm_q_kernel(const float* __restrict__ x1) {
    int idx = blockIdx.x * 256 + threadIdx.x;
    if (idx >= BDIM * HW) return;
    int b = idx / HW, p = idx - b * HW;
    const float* src = x1 + (b * CDIM) * HW + p;   // coalesced over p
    float v[CDIM];
    float ss = 0.f;
#pragma unroll
    for (int c = 0; c < CDIM; c++) { float x = src[c * HW]; v[c] = x; ss += x * x; }
    float inv = 1.f / fmaxf(sqrtf(ss), EPSN);
    float* dst = g_qn + idx * CDIM;
#pragma unroll
    for (int c = 0; c < CDIM; c++) dst[c] = v[c] * inv;
}

__global__ void norm_s_kernel(const float* __restrict__ x2) {
    int idx = blockIdx.x * 256 + threadIdx.x;
    if (idx >= NCLS * MDIM) return;
    int n = idx / MDIM, m = idx - n * MDIM;
    const float* src = x2 + (n * CDIM) * MDIM + m; // coalesced over m
    float ss = 0.f;
#pragma unroll
    for (int c = 0; c < CDIM; c++) { float x = src[c * MDIM]; ss += x * x; }
    g_rn[idx] = 1.f / fmaxf(sqrtf(ss), EPSN);
}

// ---------- fused GEMM + running top-3 ----------
__global__ void __launch_bounds__(256, 2)
fused_metric_kernel(const float* __restrict__ x2) {
    __shared__ float qs[CDIM * TQ];     // [k][qi], 16 KB
    __shared__ float ssm[KSPL * TM];    // [kk][mj], 16 KB (reused as reduce buf at end)

    const int t  = threadIdx.x;
    const int tx = t & 15;     // m-lane: owns m = tx*4..tx*4+3 and 64+tx*4..+3
    const int ty = t >> 4;     // q-lane: owns q = ty*4..ty*4+3
    const int qt = blockIdx.x, n = blockIdx.y, b = blockIdx.z;
    const int q0 = qt * TQ;

    // Load q tile [TQ][64] -> smem transposed [k][qi] (coalesced gmem; STS conflicts
    // are one-time and negligible vs the mainloop)
    for (int e = t; e < TQ * CDIM; e += 256) {
        int qi = e >> 6, k = e & 63;
        int q = q0 + qi;
        float v = (q < HW) ? g_qn[((b * HW + q) << 6) + k] : 0.f;
        qs[k * TQ + qi] = v;
    }

    float t0[4], t1[4], t2[4];
#pragma unroll
    for (int j = 0; j < 4; j++) { t0[j] = -CUDART_INF_F; t1[j] = -CUDART_INF_F; t2[j] = -CUDART_INF_F; }

    const float* x2n = x2 + ((long)(n << 6)) * MDIM;
    const float* rnn = g_rn + n * MDIM;

    for (int mt = 0; mt < NMT; mt++) {
        const int m0 = mt * TM;

        unsigned long long acc[4][4];
#pragma unroll
        for (int a = 0; a < 4; a++)
#pragma unroll
            for (int c = 0; c < 4; c++) acc[a][c] = 0ULL;

#pragma unroll
        for (int ks = 0; ks < CDIM; ks += KSPL) {
            __syncthreads();   // prev consumers done / qs ready (first iter)
            for (int e = t; e < KSPL * TM; e += 256) {
                int kk = e >> 7, mj = e & 127;
                int m = m0 + mj;
                ssm[kk * TM + mj] = (m < MDIM) ? x2n[(ks + kk) * MDIM + m] : 0.f;
            }
            __syncthreads();

            const float* qbase = qs + ks * TQ + ty * 4;
            const float* sbase = ssm + tx * 4;
#pragma unroll 8
            for (int kk = 0; kk < KSPL; kk++) {
                float4 qa = *(const float4*)(qbase + kk * TQ);
                float4 sa = *(const float4*)(sbase + kk * TM);
                float4 sb = *(const float4*)(sbase + kk * TM + 64);
                unsigned long long sp0 = pk2(sa.x, sa.y);
                unsigned long long sp1 = pk2(sa.z, sa.w);
                unsigned long long sp2 = pk2(sb.x, sb.y);
                unsigned long long sp3 = pk2(sb.z, sb.w);
                float qv[4] = {qa.x, qa.y, qa.z, qa.w};
#pragma unroll
                for (int qj = 0; qj < 4; qj++) {
                    unsigned long long qp = pk2(qv[qj], qv[qj]);
                    acc[qj][0] = ffma2(qp, sp0, acc[qj][0]);
                    acc[qj][1] = ffma2(qp, sp1, acc[qj][1]);
                    acc[qj][2] = ffma2(qp, sp2, acc[qj][2]);
                    acc[qj][3] = ffma2(qp, sp3, acc[qj][3]);
                }
            }
        }

        // Per-tile rnorm + validity mask pairs, fused into one FFMA2 each
        unsigned long long rnp[4], mkp[4];
#pragma unroll
        for (int g = 0; g < 2; g++) {
#pragma unroll
            for (int jh = 0; jh < 2; jh++) {
                int mA = m0 + g * 64 + tx * 4 + jh * 2;
                int mB = mA + 1;
                float rA = (mA < MDIM) ? rnn[mA] : 0.f;
                float rB = (mB < MDIM) ? rnn[mB] : 0.f;
                float kA = (mA < MDIM) ? 0.f : -CUDART_INF_F;
                float kB = (mB < MDIM) ? 0.f : -CUDART_INF_F;
                rnp[g * 2 + jh] = pk2(rA, rB);
                mkp[g * 2 + jh] = pk2(kA, kB);
            }
        }

        // Epilogue: scale + mask + insert into running top-3 (alu pipe, overlaps fma)
#pragma unroll
        for (int qj = 0; qj < 4; qj++) {
#pragma unroll
            for (int mp = 0; mp < 4; mp++) {
                unsigned long long v2 = ffma2(acc[qj][mp], rnp[mp], mkp[mp]);
                float lo, hi; upk2(v2, lo, hi);
                ins3(lo, t0[qj], t1[qj], t2[qj]);
                ins3(hi, t0[qj], t1[qj], t2[qj]);
            }
        }
    }

    // Merge top-3 across the 16 m-lanes (xor within half-warp; ty constant per group)
#pragma unroll
    for (int s = 1; s <= 8; s <<= 1) {
#pragma unroll
        for (int qj = 0; qj < 4; qj++) {
            float o0 = __shfl_xor_sync(0xffffffffu, t0[qj], s);
            float o1 = __shfl_xor_sync(0xffffffffu, t1[qj], s);
            float o2 = __shfl_xor_sync(0xffffffffu, t2[qj], s);
            ins3(o0, t0[qj], t1[qj], t2[qj]);
            ins3(o1, t0[qj], t1[qj], t2[qj]);
            ins3(o2, t0[qj], t1[qj], t2[qj]);
        }
    }

    // Padded q-rows are zero queries: top3 = {0,0,0} -> contribute 0. Safe to sum.
    float psum = 0.f;
#pragma unroll
    for (int qj = 0; qj < 4; qj++) psum += t0[qj] + t1[qj] + t2[qj];

    __syncthreads();                  // all warps done reading ssm before reuse
    float* red = ssm;
    if (tx == 0) red[ty] = psum;
    __syncthreads();
    if (t == 0) {
        float tot = 0.f;
#pragma unroll
        for (int i = 0; i < 16; i++) tot += red[i];
        g_part[(b * NCLS + n) * NQT + qt] = tot;
    }
}

__global__ void finalize_kernel(float* __restrict__ out) {
    int i = threadIdx.x;
    if (i < BDIM * NCLS) {
        const float* p = g_part + i * NQT;
        float s = 0.f;
#pragma unroll
        for (int j = 0; j < NQT; j++) s += p[j];
        out[i] = s;
    }
}

extern "C" void kernel_launch(void* const* d_in, const int* in_sizes, int n_in,
                              void* d_out, int out_size) {
    const float* x1 = (const float*)d_in[0];
    const float* x2 = (const float*)d_in[1];
    // d_in[2] = neighbor_k (fixed at 3 for this problem shape)
    float* out = (float*)d_out;

    norm_q_kernel<<<(BDIM * HW + 255) / 256, 256>>>(x1);
    norm_s_kernel<<<(NCLS * MDIM + 255) / 256, 256>>>(x2);
    fused_metric_kernel<<<dim3(NQT, NCLS, BDIM), 256>>>(x2);
    finalize_kernel<<<1, 192>>>(out);
}

// round 8
// speedup vs baseline: 4.3298x; 4.3298x over previous
#include <cuda_runtime.h>
#include <cuda_fp16.h>
#include <math_constants.h>

#define BDIM 16
#define CDIM 64
#define HW   441
#define NCLS 10
#define MDIM 2205
#define NQT  4
#define NMT  18
#define NSTEP 144
#define EPSN 1e-12f

#define NA4 (BDIM * 4 * 4 * 2 * 4 * 32)
#define NB4 (NCLS * 2 * NMT * 8 * 2 * 32)

__device__ float g_qn[BDIM * HW * CDIM];
__device__ float g_rn[NCLS * MDIM];
__device__ uint4 g_af[NA4];
__device__ uint4 g_bf[NB4];
__device__ float g_part[BDIM * NCLS * NQT];

__device__ __forceinline__ unsigned int h2(float lo, float hi) {
    __half2 h = __floats2half2_rn(lo, hi);
    return *reinterpret_cast<unsigned int*>(&h);
}
__device__ __forceinline__ void ins3f(float v, float &a0, float &a1, float &a2) {
    float n0 = fminf(a0, v); a0 = fmaxf(a0, v);
    float n1 = fminf(a1, n0); a1 = fmaxf(a1, n0);
    a2 = fmaxf(a2, n1);
}
// race-free: snapshot partner's triple BEFORE mutating own
__device__ __forceinline__ void merge3_shfl(int sh, float &a0, float &a1, float &a2) {
    float o0 = __shfl_xor_sync(0xffffffffu, a0, sh);
    float o1 = __shfl_xor_sync(0xffffffffu, a1, sh);
    float o2 = __shfl_xor_sync(0xffffffffu, a2, sh);
    ins3f(o0, a0, a1, a2); ins3f(o1, a0, a1, a2); ins3f(o2, a0, a1, a2);
}
__device__ __forceinline__ void mma_f16(float c[4], uint4 a, unsigned int b0, unsigned int b1) {
    asm volatile("mma.sync.aligned.m16n8k16.row.col.f32.f16.f16.f32 "
                 "{%0,%1,%2,%3},{%4,%5,%6,%7},{%8,%9},{%0,%1,%2,%3};"
                 : "+f"(c[0]), "+f"(c[1]), "+f"(c[2]), "+f"(c[3])
                 : "r"(a.x), "r"(a.y), "r"(a.z), "r"(a.w), "r"(b0), "r"(b1));
}

__global__ void norm_q_kernel(const float* __restrict__ x1) {
    int idx = blockIdx.x * 256 + threadIdx.x;
    if (idx >= BDIM * HW) return;
    int b = idx / HW, p = idx - b * HW;
    const float* src = x1 + (b * CDIM) * HW + p;
    float v[CDIM]; float ss = 0.f;
#pragma unroll
    for (int c = 0; c < CDIM; c++) { float x = src[c * HW]; v[c] = x; ss += x * x; }
    float inv = 1.f / fmaxf(sqrtf(ss), EPSN);
    float* dst = g_qn + idx * CDIM;
#pragma unroll
    for (int c = 0; c < CDIM; c++) dst[c] = v[c] * inv;
}

__global__ void norm_s_kernel(const float* __restrict__ x2) {
    int idx = blockIdx.x * 256 + threadIdx.x;
    if (idx >= NCLS * MDIM) return;
    int n = idx / MDIM, m = idx - n * MDIM;
    const float* src = x2 + (n * CDIM) * MDIM + m;
    float ss = 0.f;
#pragma unroll
    for (int c = 0; c < CDIM; c++) { float x = src[c * MDIM]; ss += x * x; }
    g_rn[idx] = 1.f / fmaxf(sqrtf(ss), EPSN);
}

__global__ void frag_kernel(const float* __restrict__ x2) {
    int idx = blockIdx.x * 256 + threadIdx.x;
    if (idx < NA4) {
        int lane = idx & 31; int r = idx >> 5;
        int kc = r & 3;  r >>= 2;
        int blk = r & 1; r >>= 1;
        int rb = r & 3;  r >>= 2;
        int qt = r & 3;  int b = r >> 2;
        int q = qt * 128 + rb * 32 + blk * 16 + (lane >> 2);
        int k = kc * 16 + 2 * (lane & 3);
        float v0=0.f,v1=0.f,v2=0.f,v3=0.f,v4=0.f,v5=0.f,v6=0.f,v7=0.f;
        if (q < HW) {
            const float* p = g_qn + (b * HW + q) * CDIM;
            v0 = p[k]; v1 = p[k+1]; v2 = p[k+8]; v3 = p[k+9];
        }
        if (q + 8 < HW) {
            const float* p = g_qn + (b * HW + q + 8) * CDIM;
            v4 = p[k]; v5 = p[k+1]; v6 = p[k+8]; v7 = p[k+9];
        }
        uint4 o; o.x = h2(v0, v1); o.y = h2(v4, v5); o.z = h2(v2, v3); o.w = h2(v6, v7);
        g_af[idx] = o;
    } else if (idx < NA4 + NB4) {
        int j = idx - NA4;
        int lane = j & 31; int r = j >> 5;
        int kcp = r & 1; r >>= 1;
        int g = r & 7;   r >>= 3;
        int mt = r % 18; r /= 18;
        int half = r & 1; int n = r >> 1;
        int m = mt * 128 + half * 64 + g * 8 + (lane >> 2);
        int k0 = kcp * 32 + 2 * (lane & 3);
        uint4 o;
        if (m < MDIM) {
            float inv = g_rn[n * MDIM + m];
            const float* base = x2 + (n * CDIM) * MDIM + m;
            o.x = h2(base[(k0)      * MDIM] * inv, base[(k0 + 1)  * MDIM] * inv);
            o.y = h2(base[(k0 + 8)  * MDIM] * inv, base[(k0 + 9)  * MDIM] * inv);
            o.z = h2(base[(k0 + 16) * MDIM] * inv, base[(k0 + 17) * MDIM] * inv);
            o.w = h2(base[(k0 + 24) * MDIM] * inv, base[(k0 + 25) * MDIM] * inv);
        } else { o.x = o.y = o.z = o.w = 0u; }
        g_bf[j] = o;
    }
}

__global__ void __launch_bounds__(256, 2)
fused_metric_kernel() {
    __shared__ float sRed[4 * 8 * 2 * 6];
    __shared__ float s_wsum[4];

    const int t = threadIdx.x;
    const int w = t >> 5, lane = t & 31, l3 = lane & 3;
    const int rb = w & 3, half = w >> 2;
    const int qt = blockIdx.x, n = blockIdx.y, b = blockIdx.z;

    uint4 aR[2][4];
    {
        const uint4* pa = g_af + ((((b * 4 + qt) * 4 + rb) * 2) * 4) * 32 + lane;
#pragma unroll
        for (int blk = 0; blk < 2; blk++)
#pragma unroll
            for (int kc = 0; kc < 4; kc++) aR[blk][kc] = pa[(blk * 4 + kc) * 32];
    }

    const uint4* baseB = g_bf + (n * 2 + half) * 9216 + lane;

    float tA[2][3], tB[2][3];
#pragma unroll
    for (int blk = 0; blk < 2; blk++)
#pragma unroll
        for (int i = 0; i < 3; i++) { tA[blk][i] = -CUDART_INF_F; tB[blk][i] = -CUDART_INF_F; }

    uint4 c0 = baseB[0], c1 = baseB[32];

#pragma unroll 1
    for (int s = 0; s < NSTEP; s++) {
        int ns = s + 1 < NSTEP ? s + 1 : NSTEP - 1;
        const uint4* pn = baseB + ns * 64;
        uint4 n0 = pn[0], n1 = pn[32];

        float acc0[4] = {0.f, 0.f, 0.f, 0.f};
        float acc1[4] = {0.f, 0.f, 0.f, 0.f};
        mma_f16(acc0, aR[0][0], c0.x, c0.y);
        mma_f16(acc0, aR[0][1], c0.z, c0.w);
        mma_f16(acc0, aR[0][2], c1.x, c1.y);
        mma_f16(acc0, aR[0][3], c1.z, c1.w);
        mma_f16(acc1, aR[1][0], c0.x, c0.y);
        mma_f16(acc1, aR[1][1], c0.z, c0.w);
        mma_f16(acc1, aR[1][2], c1.x, c1.y);
        mma_f16(acc1, aR[1][3], c1.z, c1.w);
        c0 = n0; c1 = n1;

        if (s < NSTEP - 8) {
            ins3f(acc0[0], tA[0][0], tA[0][1], tA[0][2]);
            ins3f(acc0[1], tA[0][0], tA[0][1], tA[0][2]);
            ins3f(acc0[2], tB[0][0], tB[0][1], tB[0][2]);
            ins3f(acc0[3], tB[0][0], tB[0][1], tB[0][2]);
            ins3f(acc1[0], tA[1][0], tA[1][1], tA[1][2]);
            ins3f(acc1[1], tA[1][0], tA[1][1], tA[1][2]);
            ins3f(acc1[2], tB[1][0], tB[1][1], tB[1][2]);
            ins3f(acc1[3], tB[1][0], tB[1][1], tB[1][2]);
        } else if (half == 0) {     // last tile: valid cols 0..28 (2205 = 17*128 + 29)
            int col = (s & 7) * 8 + 2 * l3;
            if (col < 29) {
                ins3f(acc0[0], tA[0][0], tA[0][1], tA[0][2]);
                ins3f(acc0[2], tB[0][0], tB[0][1], tB[0][2]);
                ins3f(acc1[0], tA[1][0], tA[1][1], tA[1][2]);
                ins3f(acc1[2], tB[1][0], tB[1][1], tB[1][2]);
            }
            if (col + 1 < 29) {
                ins3f(acc0[1], tA[0][0], tA[0][1], tA[0][2]);
                ins3f(acc0[3], tB[0][0], tB[0][1], tB[0][2]);
                ins3f(acc1[1], tA[1][0], tA[1][1], tA[1][2]);
                ins3f(acc1[3], tB[1][0], tB[1][1], tB[1][2]);
            }
        }
    }

#pragma unroll
    for (int sh = 1; sh <= 2; sh <<= 1) {
#pragma unroll
        for (int blk = 0; blk < 2; blk++) {
            merge3_shfl(sh, tA[blk][0], tA[blk][1], tA[blk][2]);
            merge3_shfl(sh, tB[blk][0], tB[blk][1], tB[blk][2]);
        }
    }

    if (w >= 4 && l3 == 0) {
#pragma unroll
        for (int blk = 0; blk < 2; blk++) {
            float* d = sRed + (((rb * 8) + (lane >> 2)) * 2 + blk) * 6;
            d[0] = tA[blk][0]; d[1] = tA[blk][1]; d[2] = tA[blk][2];
            d[3] = tB[blk][0]; d[4] = tB[blk][1]; d[5] = tB[blk][2];
        }
    }
    __syncthreads();
    if (w < 4) {
        float val = 0.f;
#pragma unroll
        for (int blk = 0; blk < 2; blk++) {
            const float* d = sRed + (((rb * 8) + (lane >> 2)) * 2 + blk) * 6;
            ins3f(d[0], tA[blk][0], tA[blk][1], tA[blk][2]);
            ins3f(d[1], tA[blk][0], tA[blk][1], tA[blk][2]);
            ins3f(d[2], tA[blk][0], tA[blk][1], tA[blk][2]);
            ins3f(d[3], tB[blk][0], tB[blk][1], tB[blk][2]);
            ins3f(d[4], tB[blk][0], tB[blk][1], tB[blk][2]);
            ins3f(d[5], tB[blk][0], tB[blk][1], tB[blk][2]);
            val += (tA[blk][0] + tA[blk][1] + tA[blk][2]) +
                   (tB[blk][0] + tB[blk][1] + tB[blk][2]);
        }
        if (l3 != 0) val = 0.f;     // one lane per row-quad contributes
#pragma unroll
        for (int sh = 16; sh > 0; sh >>= 1) val += __shfl_xor_sync(0xffffffffu, val, sh);
        if (lane == 0) s_wsum[w] = val;
    }
    __syncthreads();
    if (t == 0)
        g_part[(b * NCLS + n) * NQT + qt] = (s_wsum[0] + s_wsum[1]) + (s_wsum[2] + s_wsum[3]);
}

__global__ void finalize_kernel(float* __restrict__ out) {
    int i = threadIdx.x;
    if (i < BDIM * NCLS) {
        const float* p = g_part + i * NQT;
        out[i] = (p[0] + p[1]) + (p[2] + p[3]);
    }
}

extern "C" void kernel_launch(void* const* d_in, const int* in_sizes, int n_in,
                              void* d_out, int out_size) {
    const float* x1 = (const float*)d_in[0];
    const float* x2 = (const float*)d_in[1];
    float* out = (float*)d_out;

    norm_q_kernel<<<(BDIM * HW + 255) / 256, 256>>>(x1);
    norm_s_kernel<<<(NCLS * MDIM + 255) / 256, 256>>>(x2);
    frag_kernel<<<(NA4 + NB4 + 255) / 256, 256>>>(x2);
    fused_metric_kernel<<<dim3(NQT, NCLS, BDIM), 256>>>();
    finalize_kernel<<<1, 192>>>(out);
}

// round 10
// speedup vs baseline: 4.8751x; 1.1260x over previous
#include <cuda_runtime.h>
#include <cuda_fp16.h>
#include <math_constants.h>

#define BDIM 16
#define CDIM 64
#define HW   441
#define NCLS 10
#define MDIM 2205
#define NQT  4
#define NMT  18
#define NSTEP 144
#define EPSN 1e-12f

#define NA4 (BDIM * 4 * 4 * 2 * 4 * 32)
#define NB4 (NCLS * 2 * NMT * 8 * 2 * 32)

__device__ float g_qn[BDIM * HW * CDIM];
__device__ float g_rn[NCLS * MDIM];
__device__ uint4 g_af[NA4];
__device__ uint4 g_bf[NB4];
__device__ float g_part[BDIM * NCLS * NQT];

__device__ __forceinline__ unsigned int h2(float lo, float hi) {
    __half2 h = __floats2half2_rn(lo, hi);
    return *reinterpret_cast<unsigned int*>(&h);
}
__device__ __forceinline__ void ins3f(float v, float &a0, float &a1, float &a2) {
    float n0 = fminf(a0, v); a0 = fmaxf(a0, v);
    float n1 = fminf(a1, n0); a1 = fmaxf(a1, n0);
    a2 = fmaxf(a2, n1);
}
// race-free: snapshot partner's triple BEFORE mutating own
__device__ __forceinline__ void merge3_shfl(int sh, float &a0, float &a1, float &a2) {
    float o0 = __shfl_xor_sync(0xffffffffu, a0, sh);
    float o1 = __shfl_xor_sync(0xffffffffu, a1, sh);
    float o2 = __shfl_xor_sync(0xffffffffu, a2, sh);
    ins3f(o0, a0, a1, a2); ins3f(o1, a0, a1, a2); ins3f(o2, a0, a1, a2);
}
__device__ __forceinline__ void mma_f16(float c[4], uint4 a, unsigned int b0, unsigned int b1) {
    asm volatile("mma.sync.aligned.m16n8k16.row.col.f32.f16.f16.f32 "
                 "{%0,%1,%2,%3},{%4,%5,%6,%7},{%8,%9},{%0,%1,%2,%3};"
                 : "+f"(c[0]), "+f"(c[1]), "+f"(c[2]), "+f"(c[3])
                 : "r"(a.x), "r"(a.y), "r"(a.z), "r"(a.w), "r"(b0), "r"(b1));
}

__global__ void norm_q_kernel(const float* __restrict__ x1) {
    int idx = blockIdx.x * 256 + threadIdx.x;
    if (idx >= BDIM * HW) return;
    int b = idx / HW, p = idx - b * HW;
    const float* src = x1 + (b * CDIM) * HW + p;
    float v[CDIM]; float ss = 0.f;
#pragma unroll
    for (int c = 0; c < CDIM; c++) { float x = src[c * HW]; v[c] = x; ss += x * x; }
    float inv = 1.f / fmaxf(sqrtf(ss), EPSN);
    float* dst = g_qn + idx * CDIM;
#pragma unroll
    for (int c = 0; c < CDIM; c++) dst[c] = v[c] * inv;
}

__global__ void norm_s_kernel(const float* __restrict__ x2) {
    int idx = blockIdx.x * 256 + threadIdx.x;
    if (idx >= NCLS * MDIM) return;
    int n = idx / MDIM, m = idx - n * MDIM;
    const float* src = x2 + (n * CDIM) * MDIM + m;
    float ss = 0.f;
#pragma unroll
    for (int c = 0; c < CDIM; c++) { float x = src[c * MDIM]; ss += x * x; }
    g_rn[idx] = 1.f / fmaxf(sqrtf(ss), EPSN);
}

__global__ void frag_kernel(const float* __restrict__ x2) {
    int idx = blockIdx.x * 256 + threadIdx.x;
    if (idx < NA4) {
        int lane = idx & 31; int r = idx >> 5;
        int kc = r & 3;  r >>= 2;
        int blk = r & 1; r >>= 1;
        int rb = r & 3;  r >>= 2;
        int qt = r & 3;  int b = r >> 2;
        int q = qt * 128 + rb * 32 + blk * 16 + (lane >> 2);
        int k = kc * 16 + 2 * (lane & 3);
        float v0=0.f,v1=0.f,v2=0.f,v3=0.f,v4=0.f,v5=0.f,v6=0.f,v7=0.f;
        if (q < HW) {
            const float* p = g_qn + (b * HW + q) * CDIM;
            v0 = p[k]; v1 = p[k+1]; v2 = p[k+8]; v3 = p[k+9];
        }
        if (q + 8 < HW) {
            const float* p = g_qn + (b * HW + q + 8) * CDIM;
            v4 = p[k]; v5 = p[k+1]; v6 = p[k+8]; v7 = p[k+9];
        }
        uint4 o; o.x = h2(v0, v1); o.y = h2(v4, v5); o.z = h2(v2, v3); o.w = h2(v6, v7);
        g_af[idx] = o;
    } else if (idx < NA4 + NB4) {
        int j = idx - NA4;
        int lane = j & 31; int r = j >> 5;
        int kcp = r & 1; r >>= 1;
        int g = r & 7;   r >>= 3;
        int mt = r % 18; r /= 18;
        int half = r & 1; int n = r >> 1;
        int m = mt * 128 + half * 64 + g * 8 + (lane >> 2);
        int k0 = kcp * 32 + 2 * (lane & 3);
        uint4 o;
        if (m < MDIM) {
            float inv = g_rn[n * MDIM + m];
            const float* base = x2 + (n * CDIM) * MDIM + m;
            o.x = h2(base[(k0)      * MDIM] * inv, base[(k0 + 1)  * MDIM] * inv);
            o.y = h2(base[(k0 + 8)  * MDIM] * inv, base[(k0 + 9)  * MDIM] * inv);
            o.z = h2(base[(k0 + 16) * MDIM] * inv, base[(k0 + 17) * MDIM] * inv);
            o.w = h2(base[(k0 + 24) * MDIM] * inv, base[(k0 + 25) * MDIM] * inv);
        } else { o.x = o.y = o.z = o.w = 0u; }
        g_bf[j] = o;
    }
}

__global__ void __launch_bounds__(256, 3)
fused_metric_kernel() {
    __shared__ float sRed[4 * 8 * 2 * 6];
    __shared__ float s_wsum[4];

    const int t = threadIdx.x;
    const int w = t >> 5, lane = t & 31, l3 = lane & 3;
    const int rb = w & 3, half = w >> 2;
    const int qt = blockIdx.x, n = blockIdx.y, b = blockIdx.z;

    uint4 aR[2][4];
    {
        const uint4* pa = g_af + ((((b * 4 + qt) * 4 + rb) * 2) * 4) * 32 + lane;
#pragma unroll
        for (int blk = 0; blk < 2; blk++)
#pragma unroll
            for (int kc = 0; kc < 4; kc++) aR[blk][kc] = pa[(blk * 4 + kc) * 32];
    }

    const uint4* baseB = g_bf + (n * 2 + half) * 9216 + lane;

    float tA[2][3], tB[2][3];
#pragma unroll
    for (int blk = 0; blk < 2; blk++)
#pragma unroll
        for (int i = 0; i < 3; i++) { tA[blk][i] = -CUDART_INF_F; tB[blk][i] = -CUDART_INF_F; }

    uint4 c0 = baseB[0], c1 = baseB[32];

#pragma unroll 1
    for (int s = 0; s < NSTEP; s++) {
        int ns = s + 1 < NSTEP ? s + 1 : NSTEP - 1;
        const uint4* pn = baseB + ns * 64;
        uint4 n0 = pn[0], n1 = pn[32];

        float acc0[4] = {0.f, 0.f, 0.f, 0.f};
        float acc1[4] = {0.f, 0.f, 0.f, 0.f};
        mma_f16(acc0, aR[0][0], c0.x, c0.y);
        mma_f16(acc0, aR[0][1], c0.z, c0.w);
        mma_f16(acc0, aR[0][2], c1.x, c1.y);
        mma_f16(acc0, aR[0][3], c1.z, c1.w);
        mma_f16(acc1, aR[1][0], c0.x, c0.y);
        mma_f16(acc1, aR[1][1], c0.z, c0.w);
        mma_f16(acc1, aR[1][2], c1.x, c1.y);
        mma_f16(acc1, aR[1][3], c1.z, c1.w);
        c0 = n0; c1 = n1;

        if (s < NSTEP - 8) {
            // interleaved across the 4 independent triples for ILP
            ins3f(acc0[0], tA[0][0], tA[0][1], tA[0][2]);
            ins3f(acc0[2], tB[0][0], tB[0][1], tB[0][2]);
            ins3f(acc1[0], tA[1][0], tA[1][1], tA[1][2]);
            ins3f(acc1[2], tB[1][0], tB[1][1], tB[1][2]);
            ins3f(acc0[1], tA[0][0], tA[0][1], tA[0][2]);
            ins3f(acc0[3], tB[0][0], tB[0][1], tB[0][2]);
            ins3f(acc1[1], tA[1][0], tA[1][1], tA[1][2]);
            ins3f(acc1[3], tB[1][0], tB[1][1], tB[1][2]);
        } else if (half == 0) {     // last m-tile: valid cols 0..28 (2205 = 17*128 + 29)
            int col = (s & 7) * 8 + 2 * l3;
            if (col < 29) {
                ins3f(acc0[0], tA[0][0], tA[0][1], tA[0][2]);
                ins3f(acc0[2], tB[0][0], tB[0][1], tB[0][2]);
                ins3f(acc1[0], tA[1][0], tA[1][1], tA[1][2]);
                ins3f(acc1[2], tB[1][0], tB[1][1], tB[1][2]);
            }
            if (col + 1 < 29) {
                ins3f(acc0[1], tA[0][0], tA[0][1], tA[0][2]);
                ins3f(acc0[3], tB[0][0], tB[0][1], tB[0][2]);
                ins3f(acc1[1], tA[1][0], tA[1][1], tA[1][2]);
                ins3f(acc1[3], tB[1][0], tB[1][1], tB[1][2]);
            }
        }
    }

#pragma unroll
    for (int sh = 1; sh <= 2; sh <<= 1) {
#pragma unroll
        for (int blk = 0; blk < 2; blk++) {
            merge3_shfl(sh, tA[blk][0], tA[blk][1], tA[blk][2]);
            merge3_shfl(sh, tB[blk][0], tB[blk][1], tB[blk][2]);
        }
    }

    if (w >= 4 && l3 == 0) {
#pragma unroll
        for (int blk = 0; blk < 2; blk++) {
            float* d = sRed + (((rb * 8) + (lane >> 2)) * 2 + blk) * 6;
            d[0] = tA[blk][0]; d[1] = tA[blk][1]; d[2] = tA[blk][2];
            d[3] = tB[blk][0]; d[4] = tB[blk][1]; d[5] = tB[blk][2];
        }
    }
    __syncthreads();
    if (w < 4) {
        float val = 0.f;
#pragma unroll
        for (int blk = 0; blk < 2; blk++) {
            const float* d = sRed + (((rb * 8) + (lane >> 2)) * 2 + blk) * 6;
            ins3f(d[0], tA[blk][0], tA[blk][1], tA[blk][2]);
            ins3f(d[1], tA[blk][0], tA[blk][1], tA[blk][2]);
            ins3f(d[2], tA[blk][0], tA[blk][1], tA[blk][2]);
            ins3f(d[3], tB[blk][0], tB[blk][1], tB[blk][2]);
            ins3f(d[4], tB[blk][0], tB[blk][1], tB[blk][2]);
            ins3f(d[5], tB[blk][0], tB[blk][1], tB[blk][2]);
            val += (tA[blk][0] + tA[blk][1] + tA[blk][2]) +
                   (tB[blk][0] + tB[blk][1] + tB[blk][2]);
        }
        if (l3 != 0) val = 0.f;     // one lane per row-quad contributes
#pragma unroll
        for (int sh = 16; sh > 0; sh >>= 1) val += __shfl_xor_sync(0xffffffffu, val, sh);
        if (lane == 0) s_wsum[w] = val;
    }
    __syncthreads();
    if (t == 0)
        g_part[(b * NCLS + n) * NQT + qt] = (s_wsum[0] + s_wsum[1]) + (s_wsum[2] + s_wsum[3]);
}

__global__ void finalize_kernel(float* __restrict__ out) {
    int i = threadIdx.x;
    if (i < BDIM * NCLS) {
        const float* p = g_part + i * NQT;
        out[i] = (p[0] + p[1]) + (p[2] + p[3]);
    }
}

extern "C" void kernel_launch(void* const* d_in, const int* in_sizes, int n_in,
                              void* d_out, int out_size) {
    const float* x1 = (const float*)d_in[0];
    const float* x2 = (const float*)d_in[1];
    float* out = (float*)d_out;

    norm_q_kernel<<<(BDIM * HW + 255) / 256, 256>>>(x1);
    norm_s_kernel<<<(NCLS * MDIM + 255) / 256, 256>>>(x2);
    frag_kernel<<<(NA4 + NB4 + 255) / 256, 256>>>(x2);
    fused_metric_kernel<<<dim3(NQT, NCLS, BDIM), 256>>>();
    finalize_kernel<<<1, 192>>>(out);
}

// round 11
// speedup vs baseline: 5.6485x; 1.1586x over previous
#include <cuda_runtime.h>
#include <cuda_fp16.h>
#include <math_constants.h>

#define BDIM 16
#define CDIM 64
#define HW   441
#define NCLS 10
#define MDIM 2205
#define NQT  4
#define NMT  18
#define NSTEP 144
#define NSPL 2
#define SPLS 72
#define EPSN 1e-12f

#define NA4 (BDIM * 4 * 4 * 2 * 4 * 32)
#define NB4 (NCLS * 2 * NMT * 8 * 2 * 32)

__device__ float g_qn[BDIM * HW * CDIM];
__device__ float g_rn[NCLS * MDIM];
__device__ uint4 g_af[NA4];
__device__ uint4 g_bf[NB4];
__device__ float4 g_rowtri[BDIM * NCLS * NQT * 128 * NSPL];   // per-row top-3 per m-split

__device__ __forceinline__ unsigned int h2(float lo, float hi) {
    __half2 h = __floats2half2_rn(lo, hi);
    return *reinterpret_cast<unsigned int*>(&h);
}
__device__ __forceinline__ unsigned int maxh2(unsigned int a, unsigned int b) {
    unsigned int d; asm("max.f16x2 %0, %1, %2;" : "=r"(d) : "r"(a), "r"(b)); return d;
}
__device__ __forceinline__ unsigned int minh2(unsigned int a, unsigned int b) {
    unsigned int d; asm("min.f16x2 %0, %1, %2;" : "=r"(d) : "r"(a), "r"(b)); return d;
}
__device__ __forceinline__ void ins3p(unsigned int v, unsigned int &a0, unsigned int &a1, unsigned int &a2) {
    unsigned int n0 = minh2(a0, v); a0 = maxh2(a0, v);
    unsigned int n1 = minh2(a1, n0); a1 = maxh2(a1, n0);
    a2 = maxh2(a2, n1);
}
__device__ __forceinline__ void ins3f(float v, float &a0, float &a1, float &a2) {
    float n0 = fminf(a0, v); a0 = fmaxf(a0, v);
    float n1 = fminf(a1, n0); a1 = fmaxf(a1, n0);
    a2 = fmaxf(a2, n1);
}
// race-free packed merge: snapshot partner's triple BEFORE mutating own
__device__ __forceinline__ void merge3p_shfl(int sh, unsigned int &a0, unsigned int &a1, unsigned int &a2) {
    unsigned int o0 = __shfl_xor_sync(0xffffffffu, a0, sh);
    unsigned int o1 = __shfl_xor_sync(0xffffffffu, a1, sh);
    unsigned int o2 = __shfl_xor_sync(0xffffffffu, a2, sh);
    ins3p(o0, a0, a1, a2); ins3p(o1, a0, a1, a2); ins3p(o2, a0, a1, a2);
}
// unpack a packed fp16 value-pair and insert both halves into an fp32 triple
__device__ __forceinline__ void unp_ins(unsigned int p, float &a0, float &a1, float &a2) {
    float2 f = __half22float2(*reinterpret_cast<__half2*>(&p));
    ins3f(f.x, a0, a1, a2); ins3f(f.y, a0, a1, a2);
}
__device__ __forceinline__ void mma_f16(float c[4], uint4 a, unsigned int b0, unsigned int b1) {
    asm volatile("mma.sync.aligned.m16n8k16.row.col.f32.f16.f16.f32 "
                 "{%0,%1,%2,%3},{%4,%5,%6,%7},{%8,%9},{%0,%1,%2,%3};"
                 : "+f"(c[0]), "+f"(c[1]), "+f"(c[2]), "+f"(c[3])
                 : "r"(a.x), "r"(a.y), "r"(a.z), "r"(a.w), "r"(b0), "r"(b1));
}

__global__ void norm_q_kernel(const float* __restrict__ x1) {
    int idx = blockIdx.x * 256 + threadIdx.x;
    if (idx >= BDIM * HW) return;
    int b = idx / HW, p = idx - b * HW;
    const float* src = x1 + (b * CDIM) * HW + p;
    float v[CDIM]; float ss = 0.f;
#pragma unroll
    for (int c = 0; c < CDIM; c++) { float x = src[c * HW]; v[c] = x; ss += x * x; }
    float inv = 1.f / fmaxf(sqrtf(ss), EPSN);
    float* dst = g_qn + idx * CDIM;
#pragma unroll
    for (int c = 0; c < CDIM; c++) dst[c] = v[c] * inv;
}

__global__ void norm_s_kernel(const float* __restrict__ x2) {
    int idx = blockIdx.x * 256 + threadIdx.x;
    if (idx >= NCLS * MDIM) return;
    int n = idx / MDIM, m = idx - n * MDIM;
    const float* src = x2 + (n * CDIM) * MDIM + m;
    float ss = 0.f;
#pragma unroll
    for (int c = 0; c < CDIM; c++) { float x = src[c * MDIM]; ss += x * x; }
    g_rn[idx] = 1.f / fmaxf(sqrtf(ss), EPSN);
}

__global__ void frag_kernel(const float* __restrict__ x2) {
    int idx = blockIdx.x * 256 + threadIdx.x;
    if (idx < NA4) {
        int lane = idx & 31; int r = idx >> 5;
        int kc = r & 3;  r >>= 2;
        int blk = r & 1; r >>= 1;
        int rb = r & 3;  r >>= 2;
        int qt = r & 3;  int b = r >> 2;
        int q = qt * 128 + rb * 32 + blk * 16 + (lane >> 2);
        int k = kc * 16 + 2 * (lane & 3);
        float v0=0.f,v1=0.f,v2=0.f,v3=0.f,v4=0.f,v5=0.f,v6=0.f,v7=0.f;
        if (q < HW) {
            const float* p = g_qn + (b * HW + q) * CDIM;
            v0 = p[k]; v1 = p[k+1]; v2 = p[k+8]; v3 = p[k+9];
        }
        if (q + 8 < HW) {
            const float* p = g_qn + (b * HW + q + 8) * CDIM;
            v4 = p[k]; v5 = p[k+1]; v6 = p[k+8]; v7 = p[k+9];
        }
        uint4 o; o.x = h2(v0, v1); o.y = h2(v4, v5); o.z = h2(v2, v3); o.w = h2(v6, v7);
        g_af[idx] = o;
    } else if (idx < NA4 + NB4) {
        int j = idx - NA4;
        int lane = j & 31; int r = j >> 5;
        int kcp = r & 1; r >>= 1;
        int g = r & 7;   r >>= 3;
        int mt = r % 18; r /= 18;
        int half = r & 1; int n = r >> 1;
        int m = mt * 128 + half * 64 + g * 8 + (lane >> 2);
        int k0 = kcp * 32 + 2 * (lane & 3);
        uint4 o;
        if (m < MDIM) {
            float inv = g_rn[n * MDIM + m];
            const float* base = x2 + (n * CDIM) * MDIM + m;
            o.x = h2(base[(k0)      * MDIM] * inv, base[(k0 + 1)  * MDIM] * inv);
            o.y = h2(base[(k0 + 8)  * MDIM] * inv, base[(k0 + 9)  * MDIM] * inv);
            o.z = h2(base[(k0 + 16) * MDIM] * inv, base[(k0 + 17) * MDIM] * inv);
            o.w = h2(base[(k0 + 24) * MDIM] * inv, base[(k0 + 25) * MDIM] * inv);
        } else { o.x = o.y = o.z = o.w = 0u; }
        g_bf[j] = o;
    }
}

__global__ void __launch_bounds__(256, 3)
fused_metric_kernel() {
    __shared__ unsigned int sRed[4 * 8 * 12];   // 4 warps x 8 quads x (4 triples * 3 u32)

    const int t = threadIdx.x;
    const int w = t >> 5, lane = t & 31, l3 = lane & 3;
    const int rb = w & 3, half = w >> 2;
    const int qt = blockIdx.x >> 1, ms = blockIdx.x & 1;
    const int n = blockIdx.y, b = blockIdx.z;
    const int s0 = ms * SPLS, s1 = s0 + SPLS;

    uint4 aR[2][4];
    {
        const uint4* pa = g_af + ((((b * 4 + qt) * 4 + rb) * 2) * 4) * 32 + lane;
#pragma unroll
        for (int blk = 0; blk < 2; blk++)
#pragma unroll
            for (int kc = 0; kc < 4; kc++) aR[blk][kc] = pa[(blk * 4 + kc) * 32];
    }

    const uint4* baseB = g_bf + (n * 2 + half) * 9216 + lane;

    // packed fp16 triples: A0=row r, B0=row r+8, A1=row r+16, B1=row r+24
    unsigned int A0a = 0xFC00FC00u, A0b = 0xFC00FC00u, A0c = 0xFC00FC00u;
    unsigned int B0a = 0xFC00FC00u, B0b = 0xFC00FC00u, B0c = 0xFC00FC00u;
    unsigned int A1a = 0xFC00FC00u, A1b = 0xFC00FC00u, A1c = 0xFC00FC00u;
    unsigned int B1a = 0xFC00FC00u, B1b = 0xFC00FC00u, B1c = 0xFC00FC00u;

    uint4 c0 = baseB[s0 * 64], c1 = baseB[s0 * 64 + 32];
    const int sMask = (s1 < NSTEP - 8) ? s1 : NSTEP - 8;   // clean steps end

#pragma unroll 1
    for (int s = s0; s < s1; s++) {
        int ns = s + 1 < s1 ? s + 1 : s;
        const uint4* pn = baseB + ns * 64;
        uint4 n0 = pn[0], n1 = pn[32];

        float acc0[4] = {0.f, 0.f, 0.f, 0.f};
        float acc1[4] = {0.f, 0.f, 0.f, 0.f};
        mma_f16(acc0, aR[0][0], c0.x, c0.y);
        mma_f16(acc0, aR[0][1], c0.z, c0.w);
        mma_f16(acc0, aR[0][2], c1.x, c1.y);
        mma_f16(acc0, aR[0][3], c1.z, c1.w);
        mma_f16(acc1, aR[1][0], c0.x, c0.y);
        mma_f16(acc1, aR[1][1], c0.z, c0.w);
        mma_f16(acc1, aR[1][2], c1.x, c1.y);
        mma_f16(acc1, aR[1][3], c1.z, c1.w);
        c0 = n0; c1 = n1;

        if (s < sMask) {
            ins3p(h2(acc0[0], acc0[1]), A0a, A0b, A0c);
            ins3p(h2(acc0[2], acc0[3]), B0a, B0b, B0c);
            ins3p(h2(acc1[0], acc1[1]), A1a, A1b, A1c);
            ins3p(h2(acc1[2], acc1[3]), B1a, B1b, B1c);
        } else if (half == 0) {      // last m-tile: valid cols 0..28 (2205 = 17*128 + 29)
            const float NI = -CUDART_INF_F;
            int col = (s & 7) * 8 + 2 * l3;
            float e0 = (col < 29) ? acc0[0] : NI, e1 = (col + 1 < 29) ? acc0[1] : NI;
            float e2 = (col < 29) ? acc0[2] : NI, e3 = (col + 1 < 29) ? acc0[3] : NI;
            float e4 = (col < 29) ? acc1[0] : NI, e5 = (col + 1 < 29) ? acc1[1] : NI;
            float e6 = (col < 29) ? acc1[2] : NI, e7 = (col + 1 < 29) ? acc1[3] : NI;
            ins3p(h2(e0, e1), A0a, A0b, A0c);
            ins3p(h2(e2, e3), B0a, B0b, B0c);
            ins3p(h2(e4, e5), A1a, A1b, A1c);
            ins3p(h2(e6, e7), B1a, B1b, B1c);
        }
    }

    // quad merge (lanes l3 = 0..3 cover the 8 cols of each group)
#pragma unroll
    for (int sh = 1; sh <= 2; sh <<= 1) {
        merge3p_shfl(sh, A0a, A0b, A0c);
        merge3p_shfl(sh, B0a, B0b, B0c);
        merge3p_shfl(sh, A1a, A1b, A1c);
        merge3p_shfl(sh, B1a, B1b, B1c);
    }

    // cross-half merge via smem (w>=4 publish, w<4 combine)
    if (w >= 4 && l3 == 0) {
        unsigned int* d = sRed + (rb * 8 + (lane >> 2)) * 12;
        d[0] = A0a; d[1] = A0b; d[2]  = A0c; d[3]  = B0a; d[4]  = B0b; d[5]  = B0c;
        d[6] = A1a; d[7] = A1b; d[8]  = A1c; d[9]  = B1a; d[10] = B1b; d[11] = B1c;
    }
    __syncthreads();
    if (w < 4 && l3 == 0) {
        const unsigned int* d = sRed + (rb * 8 + (lane >> 2)) * 12;
        ins3p(d[0], A0a, A0b, A0c); ins3p(d[1], A0a, A0b, A0c); ins3p(d[2], A0a, A0b, A0c);
        ins3p(d[3], B0a, B0b, B0c); ins3p(d[4], B0a, B0b, B0c); ins3p(d[5], B0a, B0b, B0c);
        ins3p(d[6], A1a, A1b, A1c); ins3p(d[7], A1a, A1b, A1c); ins3p(d[8], A1a, A1b, A1c);
        ins3p(d[9], B1a, B1b, B1c); ins3p(d[10], B1a, B1b, B1c); ins3p(d[11], B1a, B1b, B1c);

        // unpack each packed triple (lo/hi streams) -> fp32 row triple, store
        const int entry = (b * NCLS + n) * NQT + qt;
        const int row0 = rb * 32 + (lane >> 2);
        float4* outp = g_rowtri + ((long)entry * 128) * NSPL + ms;
        {
            float u0 = -CUDART_INF_F, u1 = u0, u2 = u0;
            unp_ins(A0a, u0, u1, u2); unp_ins(A0b, u0, u1, u2); unp_ins(A0c, u0, u1, u2);
            outp[(row0) * NSPL] = make_float4(u0, u1, u2, 0.f);
        }
        {
            float u0 = -CUDART_INF_F, u1 = u0, u2 = u0;
            unp_ins(B0a, u0, u1, u2); unp_ins(B0b, u0, u1, u2); unp_ins(B0c, u0, u1, u2);
            outp[(row0 + 8) * NSPL] = make_float4(u0, u1, u2, 0.f);
        }
        {
            float u0 = -CUDART_INF_F, u1 = u0, u2 = u0;
            unp_ins(A1a, u0, u1, u2); unp_ins(A1b, u0, u1, u2); unp_ins(A1c, u0, u1, u2);
            outp[(row0 + 16) * NSPL] = make_float4(u0, u1, u2, 0.f);
        }
        {
            float u0 = -CUDART_INF_F, u1 = u0, u2 = u0;
            unp_ins(B1a, u0, u1, u2); unp_ins(B1b, u0, u1, u2); unp_ins(B1c, u0, u1, u2);
            outp[(row0 + 24) * NSPL] = make_float4(u0, u1, u2, 0.f);
        }
    }
}

// merge the NSPL split-triples per row, sum top-3, reduce over rows
__global__ void finalize_kernel(float* __restrict__ out) {
    __shared__ float red[16];
    const int e = blockIdx.x;          // b*NCLS + n
    const int q = threadIdx.x;         // 0..511
    float val = 0.f;
    if (q < HW) {
        int qt = q >> 7, row = q & 127;
        const float4* p = g_rowtri + ((long)((e * NQT + qt) * 128 + row)) * NSPL;
        float4 u = p[0], v = p[1];
        float t0 = u.x, t1 = u.y, t2 = u.z;
        ins3f(v.x, t0, t1, t2); ins3f(v.y, t0, t1, t2); ins3f(v.z, t0, t1, t2);
        val = t0 + t1 + t2;
    }
    const int w = q >> 5, lane = q & 31;
#pragma unroll
    for (int sh = 16; sh > 0; sh >>= 1) val += __shfl_xor_sync(0xffffffffu, val, sh);
    if (lane == 0) red[w] = val;
    __syncthreads();
    if (w == 0) {
        float x = (lane < 16) ? red[lane] : 0.f;
#pragma unroll
        for (int sh = 8; sh > 0; sh >>= 1) x += __shfl_xor_sync(0xffffffffu, x, sh);
        if (lane == 0) out[e] = x;
    }
}

extern "C" void kernel_launch(void* const* d_in, const int* in_sizes, int n_in,
                              void* d_out, int out_size) {
    const float* x1 = (const float*)d_in[0];
    const float* x2 = (const float*)d_in[1];
    float* out = (float*)d_out;

    norm_q_kernel<<<(BDIM * HW + 255) / 256, 256>>>(x1);
    norm_s_kernel<<<(NCLS * MDIM + 255) / 256, 256>>>(x2);
    frag_kernel<<<(NA4 + NB4 + 255) / 256, 256>>>(x2);
    fused_metric_kernel<<<dim3(NQT * NSPL, NCLS, BDIM), 256>>>();
    finalize_kernel<<<BDIM * NCLS, 512>>>(out);
}